// round 5
// baseline (speedup 1.0000x reference)
#include <cuda_runtime.h>
#include <cstdint>

#define BB 32
#define SS 128
#define UU 256
#define HH 128
#define VV 30001
#define NT_N 235             // n tiles of 128 (30080 padded)
#define NT_M 32              // m tiles of 128

__device__ float    g_outs[BB * SS * HH];        // RNN outputs [4096][128]
__device__ uint32_t g_wsB[NT_N * 16384];         // per-tile smem images: tf32 bits, swizzled

// ---------------------------------------------------------------------------
__device__ __forceinline__ uint32_t smem_u32(const void* p) {
    uint32_t a;
    asm("{ .reg .u64 t; cvta.to.shared.u64 t, %1; cvt.u32.u64 %0, t; }" : "=r"(a) : "l"(p));
    return a;
}
#define CP_ASYNC16(s, g) \
    asm volatile("cp.async.cg.shared.global [%0], [%1], 16;" :: "r"(s), "l"(g) : "memory")
#define CP_COMMIT()  asm volatile("cp.async.commit_group;" ::: "memory")
#define CP_WAIT1()   asm volatile("cp.async.wait_group 1;" ::: "memory")
#define CP_WAIT0()   asm volatile("cp.async.wait_group 0;" ::: "memory")

#define LDS128U(r0, r1, r2, r3, addr) \
    asm volatile("ld.shared.v4.u32 {%0,%1,%2,%3}, [%4];" \
                 : "=r"(r0), "=r"(r1), "=r"(r2), "=r"(r3) : "r"(addr))

__device__ __forceinline__ uint32_t cvt_tf32(float f) {
    uint32_t u;
    asm("cvt.rna.tf32.f32 %0, %1;" : "=r"(u) : "f"(f));
    return u;
}
__device__ __forceinline__ void mma_op(float* d, const uint32_t* a, uint32_t b0, uint32_t b1) {
    asm volatile("mma.sync.aligned.m16n8k8.row.col.f32.tf32.tf32.f32 "
                 "{%0,%1,%2,%3}, {%4,%5,%6,%7}, {%8,%9}, {%0,%1,%2,%3};"
                 : "+f"(d[0]), "+f"(d[1]), "+f"(d[2]), "+f"(d[3])
                 : "r"(a[0]), "r"(a[1]), "r"(a[2]), "r"(a[3]), "r"(b0), "r"(b1));
}

// ---------------------------------------------------------------------------
// Combined prep kernel: CTAs [0,32) run the RNN (one per batch);
// CTAs [32, 32+235) transpose+convert+swizzle one 128-wide n-tile of ws.
//
// B tile layout (matches GEMM smem image exactly):
//   element (n in [0,128), k in [0,128)):  c=k&3, e=(k>>2)&3, s=k>>4
//   word index = (c*128 + n)*32 + 4*(s ^ ((c<<1)|(n&1))) + e
//   value = tf32 bits of ws[k][n_global]  (0 beyond VV)
// ---------------------------------------------------------------------------
__global__ __launch_bounds__(384, 1)
void prep_kernel(const int* __restrict__ users, const int* __restrict__ items,
                 const float* __restrict__ h0,
                 const float* __restrict__ P_ru, const float* __restrict__ W_ru,
                 const float* __restrict__ b_ru,
                 const float* __restrict__ P_c, const float* __restrict__ W_c,
                 const float* __restrict__ b_c,
                 const float* __restrict__ ws)
{
    extern __shared__ float sm[];
    const int tid = threadIdx.x;

    if (blockIdx.x >= BB) {
        // ------------------- ws tile prep -------------------
        const int nt = blockIdx.x - BB;
        float (*t)[33] = (float(*)[33])sm;           // [128][33]
        const int w = tid >> 5, lane = tid & 31;
        for (int nc = 0; nc < 4; nc++) {
            __syncthreads();
            const int n0 = nt * 128 + nc * 32;
            for (int idx = tid; idx < 128 * 32; idx += 384) {
                int k = idx >> 5, j = idx & 31;
                int n = n0 + j;
                t[k][j] = (n < VV) ? ws[(size_t)k * VV + n] : 0.f;
            }
            __syncthreads();
            for (int g = w; g < 128; g += 12) {
                int c = g >> 5, j = g & 31;
                int n128 = nc * 32 + j;
                int f = (c << 1) | (n128 & 1);
                int sp = lane >> 2, e = lane & 3;
                int s = sp ^ f;
                int k = 16 * s + 4 * e + c;
                g_wsB[(size_t)nt * 16384 + (c * 128 + n128) * 32 + lane] = cvt_tf32(t[k][j]);
            }
        }
        return;
    }

    // ------------------- RNN -------------------
    float* state_s = sm;
    float* rh_s    = sm + UU * HH;
    float* z_s     = rh_s + HH;
    int*   users_s = (int*)(z_s + HH);
    int*   items_s = users_s + SS;

    const int b = blockIdx.x;

    for (int t = tid; t < SS; t += blockDim.x) {
        users_s[t] = users[b * SS + t];
        items_s[t] = items[b * SS + t];
    }
    {
        const float4* src = (const float4*)(h0 + (size_t)b * UU * HH);
        float4* dst = (float4*)state_s;
        for (int i = tid; i < UU * HH / 4; i += blockDim.x) dst[i] = src[i];
    }

    float wreg[HH];
    float breg;
    if (tid < 2 * HH) {
        #pragma unroll
        for (int k = 0; k < HH; k++) wreg[k] = W_ru[k * (2 * HH) + tid];
        breg = b_ru[tid];
    } else {
        const int j = tid - 2 * HH;
        #pragma unroll
        for (int k = 0; k < HH; k++) wreg[k] = W_c[k * HH + j];
        breg = b_c[j];
    }
    __syncthreads();

    float pA;
    {
        int it0 = items_s[0];
        pA = (tid < 2 * HH) ? P_ru[(size_t)it0 * (2 * HH) + tid]
                            : P_c[(size_t)it0 * HH + (tid - 2 * HH)];
    }

    for (int t = 0; t < SS; t++) {
        const int u = users_s[t];
        const int itn = items_s[(t + 1) & (SS - 1)];
        float pN = (tid < 2 * HH) ? P_ru[(size_t)itn * (2 * HH) + tid]
                                  : P_c[(size_t)itn * HH + (tid - 2 * HH)];

        if (tid < 2 * HH) {
            const float* hs = state_s + u * HH;
            float a0 = 0.f, a1 = 0.f, a2 = 0.f, a3 = 0.f;
            float a4 = 0.f, a5 = 0.f, a6 = 0.f, a7 = 0.f;
            #pragma unroll
            for (int k = 0; k < HH; k += 8) {
                float4 h4 = *(const float4*)(hs + k);
                float4 h5 = *(const float4*)(hs + k + 4);
                a0 += h4.x * wreg[k];     a1 += h4.y * wreg[k + 1];
                a2 += h4.z * wreg[k + 2]; a3 += h4.w * wreg[k + 3];
                a4 += h5.x * wreg[k + 4]; a5 += h5.y * wreg[k + 5];
                a6 += h5.z * wreg[k + 6]; a7 += h5.w * wreg[k + 7];
            }
            float x = pA + breg + ((a0 + a1) + (a2 + a3)) + ((a4 + a5) + (a6 + a7));
            float sgm = 1.f / (1.f + __expf(-x));
            if (tid < HH) rh_s[tid] = sgm * hs[tid];
            else          z_s[tid - HH] = sgm;
        }
        __syncthreads();

        if (tid >= 2 * HH) {
            const int j = tid - 2 * HH;
            float a0 = 0.f, a1 = 0.f, a2 = 0.f, a3 = 0.f;
            float a4 = 0.f, a5 = 0.f, a6 = 0.f, a7 = 0.f;
            #pragma unroll
            for (int k = 0; k < HH; k += 8) {
                float4 r4 = *(const float4*)(rh_s + k);
                float4 r5 = *(const float4*)(rh_s + k + 4);
                a0 += r4.x * wreg[k];     a1 += r4.y * wreg[k + 1];
                a2 += r4.z * wreg[k + 2]; a3 += r4.w * wreg[k + 3];
                a4 += r5.x * wreg[k + 4]; a5 += r5.y * wreg[k + 5];
                a6 += r5.z * wreg[k + 6]; a7 += r5.w * wreg[k + 7];
            }
            float x = pA + breg + ((a0 + a1) + (a2 + a3)) + ((a4 + a5) + (a6 + a7));
            float c = tanhf(x);
            float h_old = state_s[u * HH + j];
            float z = z_s[j];
            float hn = z * h_old + (1.f - z) * c;
            state_s[u * HH + j] = hn;
            g_outs[((size_t)b * SS + t) * HH + j] = hn;
        }
        __syncthreads();
        pA = pN;
    }
}

// ---------------------------------------------------------------------------
// Persistent GEMM: out[4096,30001] = g_outs[4096,128] @ ws
// 148 CTAs x 256 threads. A in registers across each CTA's n-run;
// B double-buffered linear 64KB cp.async of pre-swizzled tf32 tiles.
// Inner loop: 1 LDS.128 + 2 HMMA per (s,nf). Conflict-free.
// ---------------------------------------------------------------------------
#define BS_BYTES  65536
#define GEMM_SMEM (2 * BS_BYTES)
#define GRID_G 148

__device__ __forceinline__ void stage_B(uint32_t sbuf, int nt, int tid) {
    const uint32_t* src = g_wsB + (size_t)nt * 16384;
    #pragma unroll
    for (int jj = 0; jj < 16; jj++) {
        int ch = tid + jj * 256;
        CP_ASYNC16(sbuf + ch * 16, src + ch * 4);
    }
}

__device__ __forceinline__ void load_a(uint32_t a[16][4], int mt, int w, int l) {
    const float* A0 = g_outs + (size_t)(mt * 128 + w * 16 + (l >> 2)) * HH;
    const float* A1 = A0 + 8 * HH;
    #pragma unroll
    for (int ks = 0; ks < 16; ks++) {
        int k0 = ks * 8 + (l & 3);
        a[ks][0] = cvt_tf32(A0[k0]);
        a[ks][1] = cvt_tf32(A1[k0]);
        a[ks][2] = cvt_tf32(A0[k0 + 4]);
        a[ks][3] = cvt_tf32(A1[k0 + 4]);
    }
}

__global__ __launch_bounds__(256, 1)
void gemm_kernel(float* __restrict__ out)
{
    extern __shared__ uint32_t smu[];
    const int tid = threadIdx.x;
    const int w = tid >> 5, l = tid & 31;
    const uint32_t sbase = smem_u32(smu);

    const int cta = blockIdx.x;
    int t0  = cta * 50 + (cta < 120 ? cta : 120);   // 7520 = 148*50+120
    int cnt = 50 + (cta < 120 ? 1 : 0);
    int mt = t0 / NT_N;
    int nt = t0 - mt * NT_N;

    stage_B(sbase, nt, tid);
    CP_COMMIT();

    uint32_t a[16][4];
    load_a(a, mt, w, l);

    const int c = l & 3, r = l >> 2;
    const int f = (c << 1) | (r & 1);
    const uint32_t boff = (uint32_t)c * 16384 + (uint32_t)r * 128;  // bytes

    for (int i = 0; i < cnt; i++) {
        const int j = i + 1;
        const bool have_next = (j < cnt);
        int mt_j = mt, nt_j = nt + 1;
        if (nt_j == NT_N) { nt_j = 0; mt_j++; }

        if (have_next) {
            stage_B(sbase + (uint32_t)(j & 1) * BS_BYTES, nt_j, tid);
            CP_COMMIT();
            CP_WAIT1();
        } else {
            CP_WAIT0();
        }
        __syncthreads();

        float acc[16][4];
        #pragma unroll
        for (int nf = 0; nf < 16; nf++) {
            acc[nf][0] = 0.f; acc[nf][1] = 0.f; acc[nf][2] = 0.f; acc[nf][3] = 0.f;
        }

        const uint32_t Bt = sbase + (uint32_t)(i & 1) * BS_BYTES + boff;
        #pragma unroll
        for (int s = 0; s < 8; s++) {
            const uint32_t sa = Bt + ((uint32_t)(s ^ f) << 4);
            #pragma unroll
            for (int nf = 0; nf < 16; nf++) {
                uint32_t b0, b1, b2, b3;
                LDS128U(b0, b1, b2, b3, sa + (uint32_t)nf * 1024);
                mma_op(acc[nf], a[2 * s],     b0, b1);
                mma_op(acc[nf], a[2 * s + 1], b2, b3);
            }
        }

        // epilogue: registers -> gmem
        {
            size_t r0 = (size_t)(mt * 128 + w * 16 + r) * VV;
            size_t r1 = r0 + (size_t)8 * VV;
            int colb = nt * 128 + c * 2;
            if (nt < NT_N - 1) {
                #pragma unroll
                for (int nf = 0; nf < 16; nf++) {
                    int cc = colb + nf * 8;
                    out[r0 + cc]     = acc[nf][0];
                    out[r0 + cc + 1] = acc[nf][1];
                    out[r1 + cc]     = acc[nf][2];
                    out[r1 + cc + 1] = acc[nf][3];
                }
            } else {
                #pragma unroll
                for (int nf = 0; nf < 16; nf++) {
                    int cc = colb + nf * 8;
                    if (cc < VV)     { out[r0 + cc]     = acc[nf][0]; out[r1 + cc]     = acc[nf][2]; }
                    if (cc + 1 < VV) { out[r0 + cc + 1] = acc[nf][1]; out[r1 + cc + 1] = acc[nf][3]; }
                }
            }
        }
        __syncthreads();

        if (have_next && mt_j != mt) load_a(a, mt_j, w, l);
        mt = mt_j; nt = nt_j;
    }
}

// ---------------------------------------------------------------------------
#define PREP_SMEM ((UU * HH + 2 * HH) * 4 + 2 * SS * 4)   // >= 128*33*4 too

extern "C" void kernel_launch(void* const* d_in, const int* in_sizes, int n_in,
                              void* d_out, int out_size)
{
    const int*   users = (const int*)d_in[0];
    const int*   items = (const int*)d_in[1];
    const float* h0    = (const float*)d_in[2];
    const float* P_ru  = (const float*)d_in[3];
    const float* W_ru  = (const float*)d_in[4];
    const float* b_ru  = (const float*)d_in[5];
    const float* P_c   = (const float*)d_in[6];
    const float* W_c   = (const float*)d_in[7];
    const float* b_c   = (const float*)d_in[8];
    const float* ws    = (const float*)d_in[9];
    float* out = (float*)d_out;

    static int attr_done = 0;
    if (!attr_done) {
        cudaFuncSetAttribute(prep_kernel, cudaFuncAttributeMaxDynamicSharedMemorySize, PREP_SMEM);
        cudaFuncSetAttribute(gemm_kernel, cudaFuncAttributeMaxDynamicSharedMemorySize, GEMM_SMEM);
        attr_done = 1;
    }

    prep_kernel<<<BB + NT_N, 384, PREP_SMEM>>>(users, items, h0, P_ru, W_ru, b_ru,
                                               P_c, W_c, b_c, ws);
    gemm_kernel<<<GRID_G, 256, GEMM_SMEM>>>(out);
}

// round 7
// speedup vs baseline: 1.5563x; 1.5563x over previous
#include <cuda_runtime.h>
#include <cstdint>

#define BB 32
#define SS 128
#define UU 256
#define HH 128
#define VV 30001
#define NT_N 469             // n tiles of 64 (469*64 = 30016 >= 30001)
#define NT_M 32              // m tiles of 128
#define NTILES (NT_M * NT_N) // 15008

__device__ float    g_outs[BB * SS * HH];     // RNN outputs [4096][128]
__device__ uint32_t g_wsB[NT_N * 8192];       // per-tile smem images: tf32 bits, swizzled

// ---------------------------------------------------------------------------
__device__ __forceinline__ uint32_t smem_u32(const void* p) {
    uint32_t a;
    asm("{ .reg .u64 t; cvta.to.shared.u64 t, %1; cvt.u32.u64 %0, t; }" : "=r"(a) : "l"(p));
    return a;
}
#define CP_ASYNC16(s, g) \
    asm volatile("cp.async.cg.shared.global [%0], [%1], 16;" :: "r"(s), "l"(g) : "memory")
#define CP_COMMIT()  asm volatile("cp.async.commit_group;" ::: "memory")
#define CP_WAIT1()   asm volatile("cp.async.wait_group 1;" ::: "memory")
#define CP_WAIT0()   asm volatile("cp.async.wait_group 0;" ::: "memory")

#define LDS128U(r0, r1, r2, r3, addr) \
    asm volatile("ld.shared.v4.u32 {%0,%1,%2,%3}, [%4];" \
                 : "=r"(r0), "=r"(r1), "=r"(r2), "=r"(r3) : "r"(addr))

__device__ __forceinline__ uint32_t cvt_tf32(float f) {
    uint32_t u;
    asm("cvt.rna.tf32.f32 %0, %1;" : "=r"(u) : "f"(f));
    return u;
}
__device__ __forceinline__ void mma_op(float* d, const uint32_t* a, uint32_t b0, uint32_t b1) {
    asm volatile("mma.sync.aligned.m16n8k8.row.col.f32.tf32.tf32.f32 "
                 "{%0,%1,%2,%3}, {%4,%5,%6,%7}, {%8,%9}, {%0,%1,%2,%3};"
                 : "+f"(d[0]), "+f"(d[1]), "+f"(d[2]), "+f"(d[3])
                 : "r"(a[0]), "r"(a[1]), "r"(a[2]), "r"(a[3]), "r"(b0), "r"(b1));
}

// ---------------------------------------------------------------------------
// prep: build g_wsB. One CTA per 64-col n-tile. 256 threads.
// Image word idx W = c*2048 + n*32 + sp*4 + e holds tf32(ws[k][n0+n]),
//   k = 16*(sp^f) + 4*e + c,  f = (c<<1)|(n&1).
// ---------------------------------------------------------------------------
__global__ __launch_bounds__(256, 4)
void prep_ws(const float* __restrict__ ws)
{
    __shared__ float t[128][64];
    const int nt  = blockIdx.x;
    const int tid = threadIdx.x;
    const int n0  = nt * 64;

    for (int idx = tid; idx < 8192; idx += 256) {
        int k = idx >> 6, j = idx & 63;
        int n = n0 + j;
        t[k][j] = (n < VV) ? ws[(size_t)k * VV + n] : 0.f;
    }
    __syncthreads();

    uint32_t* dst = g_wsB + (size_t)nt * 8192;
    for (int W = tid; W < 8192; W += 256) {
        int e  = W & 3;
        int sp = (W >> 2) & 7;
        int n  = (W >> 5) & 63;
        int c  = W >> 11;
        int f  = (c << 1) | (n & 1);
        int k  = 16 * (sp ^ f) + 4 * e + c;
        dst[W] = cvt_tf32(t[k][n]);
    }
}

// ---------------------------------------------------------------------------
// RNN: one CTA per batch, 384 threads, state in smem, W columns in registers,
// next-step P rows prefetched one iteration ahead.
// ---------------------------------------------------------------------------
__global__ __launch_bounds__(384, 1)
void rnn_kernel(const int* __restrict__ users, const int* __restrict__ items,
                const float* __restrict__ h0,
                const float* __restrict__ P_ru, const float* __restrict__ W_ru,
                const float* __restrict__ b_ru,
                const float* __restrict__ P_c, const float* __restrict__ W_c,
                const float* __restrict__ b_c)
{
    extern __shared__ float sm[];
    float* state_s = sm;
    float* rh_s    = sm + UU * HH;
    float* z_s     = rh_s + HH;
    int*   users_s = (int*)(z_s + HH);
    int*   items_s = users_s + SS;

    const int b   = blockIdx.x;
    const int tid = threadIdx.x;

    for (int t = tid; t < SS; t += blockDim.x) {
        users_s[t] = users[b * SS + t];
        items_s[t] = items[b * SS + t];
    }
    {
        const float4* src = (const float4*)(h0 + (size_t)b * UU * HH);
        float4* dst = (float4*)state_s;
        for (int i = tid; i < UU * HH / 4; i += blockDim.x) dst[i] = src[i];
    }

    float wreg[HH];
    float breg;
    if (tid < 2 * HH) {
        #pragma unroll
        for (int k = 0; k < HH; k++) wreg[k] = W_ru[k * (2 * HH) + tid];
        breg = b_ru[tid];
    } else {
        const int j = tid - 2 * HH;
        #pragma unroll
        for (int k = 0; k < HH; k++) wreg[k] = W_c[k * HH + j];
        breg = b_c[j];
    }
    __syncthreads();

    float pA;
    {
        int it0 = items_s[0];
        pA = (tid < 2 * HH) ? P_ru[(size_t)it0 * (2 * HH) + tid]
                            : P_c[(size_t)it0 * HH + (tid - 2 * HH)];
    }

    for (int t = 0; t < SS; t++) {
        const int u = users_s[t];
        const int itn = items_s[(t + 1) & (SS - 1)];
        float pN = (tid < 2 * HH) ? P_ru[(size_t)itn * (2 * HH) + tid]
                                  : P_c[(size_t)itn * HH + (tid - 2 * HH)];

        if (tid < 2 * HH) {
            const float* hs = state_s + u * HH;
            float a0 = 0.f, a1 = 0.f, a2 = 0.f, a3 = 0.f;
            float a4 = 0.f, a5 = 0.f, a6 = 0.f, a7 = 0.f;
            #pragma unroll
            for (int k = 0; k < HH; k += 8) {
                float4 h4 = *(const float4*)(hs + k);
                float4 h5 = *(const float4*)(hs + k + 4);
                a0 += h4.x * wreg[k];     a1 += h4.y * wreg[k + 1];
                a2 += h4.z * wreg[k + 2]; a3 += h4.w * wreg[k + 3];
                a4 += h5.x * wreg[k + 4]; a5 += h5.y * wreg[k + 5];
                a6 += h5.z * wreg[k + 6]; a7 += h5.w * wreg[k + 7];
            }
            float x = pA + breg + ((a0 + a1) + (a2 + a3)) + ((a4 + a5) + (a6 + a7));
            float sgm = 1.f / (1.f + __expf(-x));
            if (tid < HH) rh_s[tid] = sgm * hs[tid];
            else          z_s[tid - HH] = sgm;
        }
        __syncthreads();

        if (tid >= 2 * HH) {
            const int j = tid - 2 * HH;
            float a0 = 0.f, a1 = 0.f, a2 = 0.f, a3 = 0.f;
            float a4 = 0.f, a5 = 0.f, a6 = 0.f, a7 = 0.f;
            #pragma unroll
            for (int k = 0; k < HH; k += 8) {
                float4 r4 = *(const float4*)(rh_s + k);
                float4 r5 = *(const float4*)(rh_s + k + 4);
                a0 += r4.x * wreg[k];     a1 += r4.y * wreg[k + 1];
                a2 += r4.z * wreg[k + 2]; a3 += r4.w * wreg[k + 3];
                a4 += r5.x * wreg[k + 4]; a5 += r5.y * wreg[k + 5];
                a6 += r5.z * wreg[k + 6]; a7 += r5.w * wreg[k + 7];
            }
            float x = pA + breg + ((a0 + a1) + (a2 + a3)) + ((a4 + a5) + (a6 + a7));
            float c = tanhf(x);
            float h_old = state_s[u * HH + j];
            float z = z_s[j];
            float hn = z * h_old + (1.f - z) * c;
            state_s[u * HH + j] = hn;
            g_outs[((size_t)b * SS + t) * HH + j] = hn;
        }
        __syncthreads();
        pA = pN;
    }
}

// ---------------------------------------------------------------------------
// Persistent GEMM: out[4096,30001] = g_outs[4096,128] @ ws
// 296 CTAs (2/SM) x 256 threads. CTA tile 128M x 64N, warp tile 16M x 64N.
// A in registers across each CTA's n-run; B double-buffered 32KB cp.async.
// Inner loop: 64 x (1 LDS.128 + 2 HMMA), depth-2 b-prefetch.
// ---------------------------------------------------------------------------
#define BS_BYTES  32768
#define GEMM_SMEM (2 * BS_BYTES)     // 64KB/CTA -> 2 CTAs/SM
#define GRID_G 296

__device__ __forceinline__ void stage_B(uint32_t sbuf, int nt, int tid) {
    const uint32_t* src = g_wsB + (size_t)nt * 8192;
    #pragma unroll
    for (int jj = 0; jj < 8; jj++) {
        int ch = tid + jj * 256;
        CP_ASYNC16(sbuf + ch * 16, src + ch * 4);
    }
}

__device__ __forceinline__ void load_a(uint32_t a[16][4], int mt, int w, int l) {
    const float* A0 = g_outs + (size_t)(mt * 128 + w * 16 + (l >> 2)) * HH;
    const float* A1 = A0 + 8 * HH;
    #pragma unroll
    for (int ks = 0; ks < 16; ks++) {
        int k0 = ks * 8 + (l & 3);
        a[ks][0] = cvt_tf32(A0[k0]);
        a[ks][1] = cvt_tf32(A1[k0]);
        a[ks][2] = cvt_tf32(A0[k0 + 4]);
        a[ks][3] = cvt_tf32(A1[k0 + 4]);
    }
}

__global__ __launch_bounds__(256, 2)
void gemm_kernel(float* __restrict__ out)
{
    extern __shared__ uint32_t smu[];
    const int tid = threadIdx.x;
    const int w = tid >> 5, l = tid & 31;
    const uint32_t sbase = smem_u32(smu);

    const int cta = blockIdx.x;
    // 15008 = 296*50 + 208 -> first 208 CTAs take 51
    int t0  = cta * 50 + (cta < 208 ? cta : 208);
    int cnt = 50 + (cta < 208 ? 1 : 0);
    int mt = t0 / NT_N;
    int nt = t0 - mt * NT_N;

    stage_B(sbase, nt, tid);
    CP_COMMIT();

    uint32_t a[16][4];
    load_a(a, mt, w, l);

    const int c = l & 3, r = l >> 2;
    const int f = (c << 1) | (r & 1);
    const uint32_t boff = (uint32_t)c * 8192 + (uint32_t)r * 128;   // bytes

    for (int i = 0; i < cnt; i++) {
        const int j = i + 1;
        const bool have_next = (j < cnt);
        int mt_j = mt, nt_j = nt + 1;
        if (nt_j == NT_N) { nt_j = 0; mt_j++; }

        if (have_next) {
            stage_B(sbase + (uint32_t)((j & 1) ? BS_BYTES : 0), nt_j, tid);
            CP_COMMIT();
            CP_WAIT1();
        } else {
            CP_WAIT0();
        }
        __syncthreads();

        float acc[8][4];
        #pragma unroll
        for (int nf = 0; nf < 8; nf++) {
            acc[nf][0] = 0.f; acc[nf][1] = 0.f; acc[nf][2] = 0.f; acc[nf][3] = 0.f;
        }

        const uint32_t Bt = sbase + (uint32_t)((i & 1) ? BS_BYTES : 0) + boff;
        // flat 64 iterations: it = s2*8 + nf ; depth-2 rotating prefetch
        uint32_t bq[3][4];
        LDS128U(bq[0][0], bq[0][1], bq[0][2], bq[0][3], Bt + ((uint32_t)(0 ^ f) << 4));
        LDS128U(bq[1][0], bq[1][1], bq[1][2], bq[1][3], Bt + 1024 + ((uint32_t)(0 ^ f) << 4));
        #pragma unroll
        for (int it = 0; it < 64; it++) {
            const int cur = it % 3;
            if (it < 62) {
                const int i2 = it + 2;
                const int s2n = i2 >> 3, nfn = i2 & 7;
                const int pn = i2 % 3;
                LDS128U(bq[pn][0], bq[pn][1], bq[pn][2], bq[pn][3],
                        Bt + (uint32_t)nfn * 1024 + ((uint32_t)(s2n ^ f) << 4));
            }
            const int s2 = it >> 3, nf = it & 7;
            mma_op(acc[nf], a[2 * s2],     bq[cur][0], bq[cur][1]);
            mma_op(acc[nf], a[2 * s2 + 1], bq[cur][2], bq[cur][3]);
        }

        // epilogue: registers -> gmem
        {
            size_t r0 = (size_t)(mt * 128 + w * 16 + r) * VV;
            size_t r1 = r0 + (size_t)8 * VV;
            int colb = nt * 64 + c * 2;
            if (nt < NT_N - 1) {
                #pragma unroll
                for (int nf = 0; nf < 8; nf++) {
                    int cc = colb + nf * 8;
                    out[r0 + cc]     = acc[nf][0];
                    out[r0 + cc + 1] = acc[nf][1];
                    out[r1 + cc]     = acc[nf][2];
                    out[r1 + cc + 1] = acc[nf][3];
                }
            } else {
                #pragma unroll
                for (int nf = 0; nf < 8; nf++) {
                    int cc = colb + nf * 8;
                    if (cc < VV)     { out[r0 + cc]     = acc[nf][0]; out[r1 + cc]     = acc[nf][2]; }
                    if (cc + 1 < VV) { out[r0 + cc + 1] = acc[nf][1]; out[r1 + cc + 1] = acc[nf][3]; }
                }
            }
        }
        __syncthreads();

        if (have_next && mt_j != mt) load_a(a, mt_j, w, l);
        mt = mt_j; nt = nt_j;
    }
}

// ---------------------------------------------------------------------------
#define RNN_SMEM ((UU * HH + 2 * HH) * 4 + 2 * SS * 4)

extern "C" void kernel_launch(void* const* d_in, const int* in_sizes, int n_in,
                              void* d_out, int out_size)
{
    const int*   users = (const int*)d_in[0];
    const int*   items = (const int*)d_in[1];
    const float* h0    = (const float*)d_in[2];
    const float* P_ru  = (const float*)d_in[3];
    const float* W_ru  = (const float*)d_in[4];
    const float* b_ru  = (const float*)d_in[5];
    const float* P_c   = (const float*)d_in[6];
    const float* W_c   = (const float*)d_in[7];
    const float* b_c   = (const float*)d_in[8];
    const float* ws    = (const float*)d_in[9];
    float* out = (float*)d_out;

    static int attr_done = 0;
    if (!attr_done) {
        cudaFuncSetAttribute(rnn_kernel,  cudaFuncAttributeMaxDynamicSharedMemorySize, RNN_SMEM);
        cudaFuncSetAttribute(gemm_kernel, cudaFuncAttributeMaxDynamicSharedMemorySize, GEMM_SMEM);
        attr_done = 1;
    }

    prep_ws<<<NT_N, 256>>>(ws);
    rnn_kernel<<<BB, 384, RNN_SMEM>>>(users, items, h0, P_ru, W_ru, b_ru, P_c, W_c, b_c);
    gemm_kernel<<<GRID_G, 256, GEMM_SMEM>>>(out);
}